// round 3
// baseline (speedup 1.0000x reference)
#include <cuda_runtime.h>
#include <cstdint>

#define B_  32
#define N_  4096
#define S_  512
#define K_  24
#define D_  64
#define CO_ 128
#define FINF 3.402823466e38f

// ---------------- device scratch (no allocs allowed) ----------------
__device__ int   g_fps[B_ * S_];
__device__ int   g_knn[B_ * S_ * K_];
__device__ float g_F [(size_t)B_ * N_ * CO_];      // 64 MB: per-point projection by W1a
__device__ float g_t2[B_ * S_ * CO_];              // per-center projection by (W1b - W1a)
__device__ float g_mx[B_ * S_ * CO_];
__device__ float g_mn[B_ * S_ * CO_];
__device__ float g_sm[B_ * S_ * CO_];
__device__ float g_sq[B_ * S_ * CO_];
__device__ float g_part[128 * 128];
__device__ float g_partq[128 * 128];
__device__ float g_a[CO_];
__device__ float g_b[CO_];

// Pack (dist, index) into one u64 so argmax+tiebreak is a single max.
// dist >= 0 -> float bits are order-preserving. Lower index wins ties ->
// store (4095 - p) in low bits so larger packed value = lower p.
__device__ __forceinline__ unsigned long long packdi(float d, int p) {
    return ((unsigned long long)__float_as_uint(d) << 32) | (unsigned)(4095 - p);
}

// ---------------- 1. Furthest point sampling: one block per batch ----------------
__global__ __launch_bounds__(512) void fps_kernel(const float* __restrict__ coords)
{
    int b = blockIdx.x, t = threadIdx.x;
    const float* cb = coords + (size_t)b * N_ * 3;

    float px[8], py[8], pz[8], dd[8];
#pragma unroll
    for (int j = 0; j < 8; j++) {
        int p = t + j * 512;
        px[j] = cb[p * 3 + 0];
        py[j] = cb[p * 3 + 1];
        pz[j] = cb[p * 3 + 2];
        dd[j] = 1e10f;
    }

    __shared__ unsigned long long sk[16];
    __shared__ unsigned long long sbk;   // broadcast winner key

    if (t == 0) g_fps[b * S_] = 0;
    int bi = 0;                          // current winner index (all threads agree)

    for (int it = 1; it < S_; it++) {
        // all threads load winner coords from the same address -> L1 broadcast
        float cx = cb[bi * 3 + 0], cy = cb[bi * 3 + 1], cz = cb[bi * 3 + 2];
        unsigned long long bk = 0;
#pragma unroll
        for (int j = 0; j < 8; j++) {
            float dx = px[j] - cx, dy = py[j] - cy, dz = pz[j] - cz;
            float d = dx * dx + dy * dy + dz * dz;
            d = fminf(dd[j], d);
            dd[j] = d;
            unsigned long long k = packdi(d, t + j * 512);
            bk = (k > bk) ? k : bk;
        }
#pragma unroll
        for (int off = 16; off > 0; off >>= 1) {
            unsigned long long ok = __shfl_down_sync(0xffffffffu, bk, off);
            bk = (ok > bk) ? ok : bk;
        }
        if ((t & 31) == 0) sk[t >> 5] = bk;
        __syncthreads();
        if (t < 32) {
            unsigned long long bk2 = (t < 16) ? sk[t] : 0ull;
#pragma unroll
            for (int off = 8; off > 0; off >>= 1) {
                unsigned long long ok = __shfl_down_sync(0xffffffffu, bk2, off);
                bk2 = (ok > bk2) ? ok : bk2;
            }
            if (t == 0) {
                sbk = bk2;
                g_fps[b * S_ + it] = 4095 - (int)(bk2 & 0xffffffffu);
            }
        }
        __syncthreads();
        bi = 4095 - (int)(sbk & 0xffffffffu);
    }
}

// ---------------- 2. KNN: warp per center, swizzled smem d2, 24x warp-argmin ----------------
__device__ __forceinline__ int swz(int p) { return p ^ ((p >> 5) & 31); }

__global__ __launch_bounds__(64) void knn_kernel(const float* __restrict__ coords)
{
    __shared__ float sd2[2][N_];
    int b  = blockIdx.y;
    int w  = threadIdx.x >> 5, ln = threadIdx.x & 31;
    int s  = blockIdx.x * 2 + w;
    const float* cb = coords + (size_t)b * N_ * 3;

    int ci = g_fps[b * S_ + s];
    float cx = cb[ci * 3 + 0], cy = cb[ci * 3 + 1], cz = cb[ci * 3 + 2];
    float c2 = cx * cx + cy * cy + cz * cz;

    float* D = sd2[w];
    float bd = FINF; int bi = 0x7fffffff;
    for (int j = 0; j < 128; j++) {
        int p = j * 32 + ln;                       // lane owns p == ln (mod 32)
        float x = cb[p * 3 + 0], y = cb[p * 3 + 1], z = cb[p * 3 + 2];
        float p2  = x * x + y * y + z * z;
        float dot = cx * x + cy * y + cz * z;
        float d   = c2 + p2 - 2.f * dot;           // mirror reference formula
        D[swz(p)] = d;
        if (d < bd) { bd = d; bi = p; }            // ascending p -> first-tie kept
    }
    __syncwarp();

    int* out = g_knn + (size_t)(b * S_ + s) * K_;
    for (int r = 0; r < K_; r++) {
        float rd = bd; int ri = bi;
#pragma unroll
        for (int off = 16; off > 0; off >>= 1) {
            float od = __shfl_down_sync(0xffffffffu, rd, off);
            int   oi = __shfl_down_sync(0xffffffffu, ri, off);
            if (od < rd || (od == rd && oi < ri)) { rd = od; ri = oi; }
        }
        ri = __shfl_sync(0xffffffffu, ri, 0);
        if (ln == 0) { out[r] = ri; D[swz(ri)] = FINF; }
        int wl = ri & 31;
        __syncwarp();
        // cooperative conflict-free rescan of winner lane's chunk {wl + 32*i}
        float nd = FINF; int ni = 0x7fffffff;
#pragma unroll
        for (int q = 0; q < 4; q++) {
            int i = ln + 32 * q;
            int p = wl + 32 * i;
            float d = D[swz(p)];
            if (d < nd || (d == nd && p < ni)) { nd = d; ni = p; }
        }
#pragma unroll
        for (int off = 16; off > 0; off >>= 1) {
            float od = __shfl_down_sync(0xffffffffu, nd, off);
            int   oi = __shfl_down_sync(0xffffffffu, ni, off);
            if (od < nd || (od == nd && oi < ni)) { nd = od; ni = oi; }
        }
        nd = __shfl_sync(0xffffffffu, nd, 0);
        ni = __shfl_sync(0xffffffffu, ni, 0);
        if (ln == wl) { bd = nd; bi = ni; }
        __syncwarp();
    }
}

// ---------------- 3. F[b,n,o] = sum_c x[b,c,n] * W1[o,c]  (c < 64) ----------------
__global__ __launch_bounds__(256) void gemm_kernel(const float* __restrict__ x,
                                                   const float* __restrict__ W1)
{
    __shared__ float xs[64 * 64];     // [c][n] tile, 16 KB
    __shared__ float ws[64 * 128];    // [c][o],     32 KB
    int b  = blockIdx.y;
    int n0 = blockIdx.x * 64;
    const float* xb = x + (size_t)b * D_ * N_;

    for (int e = threadIdx.x; e < 4096; e += 256) {
        int c = e >> 6, n = e & 63;
        xs[e] = xb[c * N_ + n0 + n];
    }
    for (int e = threadIdx.x; e < 8192; e += 256) {
        int o = e >> 6, c = e & 63;
        ws[c * 128 + o] = W1[o * 128 + c];
    }
    __syncthreads();

    int to = (threadIdx.x & 15) * 4;
    int tn = (threadIdx.x >> 4) * 4;
    float acc[4][8] = {};
#pragma unroll 8
    for (int c = 0; c < 64; c++) {
        float4 A  = *(const float4*)&xs[c * 64 + tn];
        float4 B0 = *(const float4*)&ws[c * 128 + to];
        float4 B1 = *(const float4*)&ws[c * 128 + to + 64];
        float a[4]  = {A.x, A.y, A.z, A.w};
        float bb[8] = {B0.x, B0.y, B0.z, B0.w, B1.x, B1.y, B1.z, B1.w};
#pragma unroll
        for (int i = 0; i < 4; i++)
#pragma unroll
            for (int j = 0; j < 8; j++)
                acc[i][j] = fmaf(a[i], bb[j], acc[i][j]);
    }

    float* Fb = g_F + ((size_t)b * N_ + n0) * CO_;
#pragma unroll
    for (int i = 0; i < 4; i++) {
        float4 v0 = {acc[i][0], acc[i][1], acc[i][2], acc[i][3]};
        float4 v1 = {acc[i][4], acc[i][5], acc[i][6], acc[i][7]};
        *(float4*)&Fb[(tn + i) * 128 + to]      = v0;
        *(float4*)&Fb[(tn + i) * 128 + to + 64] = v1;
    }
}

// ---------------- 4. t2[b,s,o] = sum_c x[b,c,fps] * (W1[o,64+c] - W1[o,c]) ----------------
__global__ __launch_bounds__(256) void t2_kernel(const float* __restrict__ x,
                                                 const float* __restrict__ W1)
{
    __shared__ float wd[64 * 128];
    __shared__ float cf[32 * 64];
    __shared__ int   sidx[32];
    int b = blockIdx.y, sg = blockIdx.x;

    if (threadIdx.x < 32) sidx[threadIdx.x] = g_fps[b * S_ + sg * 32 + threadIdx.x];
    for (int e = threadIdx.x; e < 8192; e += 256) {
        int o = e >> 6, c = e & 63;
        wd[c * 128 + o] = W1[o * 128 + 64 + c] - W1[o * 128 + c];
    }
    __syncthreads();
    const float* xb = x + (size_t)b * D_ * N_;
    for (int e = threadIdx.x; e < 2048; e += 256) {
        int sl = e >> 6, c = e & 63;
        cf[e] = xb[c * N_ + sidx[sl]];
    }
    __syncthreads();

    int o = threadIdx.x & 127, half = threadIdx.x >> 7;
    for (int sl = half; sl < 32; sl += 2) {
        float acc = 0.f;
#pragma unroll 8
        for (int c = 0; c < 64; c++)
            acc = fmaf(cf[sl * 64 + c], wd[c * 128 + o], acc);
        g_t2[(size_t)(b * S_ + sg * 32 + sl) * CO_ + o] = acc;
    }
}

// ---------------- 5. gather per (b,s): max/min/sum/sumsq over the K neighbors ----------------
__global__ __launch_bounds__(128) void gather_kernel()
{
    int b = blockIdx.y, s = blockIdx.x, o = threadIdx.x;
    __shared__ int si[K_];
    size_t row = (size_t)(b * S_ + s);
    if (o < K_) si[o] = g_knn[row * K_ + o];
    __syncthreads();

    float tv = g_t2[row * CO_ + o];
    const float* Fb = g_F + (size_t)b * N_ * CO_;
    float vmx = -FINF, vmn = FINF, vs = 0.f, vq = 0.f;
#pragma unroll
    for (int k = 0; k < K_; k++) {
        float h = Fb[(size_t)si[k] * CO_ + o] + tv;
        vmx = fmaxf(vmx, h);
        vmn = fminf(vmn, h);
        vs += h;
        vq = fmaf(h, h, vq);
    }
    g_mx[row * CO_ + o] = vmx;
    g_mn[row * CO_ + o] = vmn;
    g_sm[row * CO_ + o] = vs;
    g_sq[row * CO_ + o] = vq;
}

// ---------------- 6. deterministic channel reductions -> BN affine coefficients ----------------
__global__ __launch_bounds__(128) void red1_kernel()
{
    int j = blockIdx.x, o = threadIdx.x;
    float s1 = 0.f, s2 = 0.f;
    for (int r = 0; r < 128; r++) {
        size_t row = (size_t)j * 128 + r;
        s1 += g_sm[row * CO_ + o];
        s2 += g_sq[row * CO_ + o];
    }
    g_part [j * 128 + o] = s1;
    g_partq[j * 128 + o] = s2;
}

__global__ __launch_bounds__(128) void red2_kernel(const float* __restrict__ gamma,
                                                   const float* __restrict__ beta)
{
    int o = threadIdx.x;
    float s1 = 0.f, s2 = 0.f;
    for (int j = 0; j < 128; j++) {
        s1 += g_part [j * 128 + o];
        s2 += g_partq[j * 128 + o];
    }
    float inv  = 1.f / ((float)B_ * (float)S_ * (float)K_);
    float mean = s1 * inv;
    float var  = fmaxf(s2 * inv - mean * mean, 0.f);
    float a    = gamma[o] * rsqrtf(var + 1e-5f);
    g_a[o] = a;
    g_b[o] = beta[o] - mean * a;
}

// ---------------- 7. apply BN+ReLU to max (or min if scale<0), transpose to [B,128,S] ----------------
__global__ __launch_bounds__(256) void final_kernel(float* __restrict__ out)
{
    __shared__ float tile[64 * 129];
    __shared__ float sa[128], sb[128];
    int b = blockIdx.y;
    int s0 = blockIdx.x * 64;
    if (threadIdx.x < 128) { sa[threadIdx.x] = g_a[threadIdx.x]; sb[threadIdx.x] = g_b[threadIdx.x]; }
    __syncthreads();

    for (int e = threadIdx.x; e < 8192; e += 256) {
        int sl = e >> 7, o = e & 127;
        size_t row = (size_t)(b * S_ + s0 + sl) * CO_ + o;
        float a = sa[o];
        float h = (a >= 0.f) ? g_mx[row] : g_mn[row];
        tile[sl * 129 + o] = fmaxf(fmaf(h, a, sb[o]), 0.f);
    }
    __syncthreads();
    for (int e = threadIdx.x; e < 8192; e += 256) {
        int o = e >> 6, sl = e & 63;
        out[((size_t)b * CO_ + o) * S_ + s0 + sl] = tile[sl * 129 + o];
    }
}

// ---------------- launch ----------------
extern "C" void kernel_launch(void* const* d_in, const int* in_sizes, int n_in,
                              void* d_out, int out_size)
{
    (void)in_sizes; (void)n_in; (void)out_size;
    const float* x      = (const float*)d_in[0];
    const float* coords = (const float*)d_in[1];
    const float* W1     = (const float*)d_in[2];
    const float* gamma  = (const float*)d_in[3];
    const float* beta   = (const float*)d_in[4];
    float* out = (float*)d_out;

    gemm_kernel  <<<dim3(N_ / 64, B_), 256>>>(x, W1);
    fps_kernel   <<<B_, 512>>>(coords);
    knn_kernel   <<<dim3(S_ / 2, B_), 64>>>(coords);
    t2_kernel    <<<dim3(S_ / 32, B_), 256>>>(x, W1);
    gather_kernel<<<dim3(S_, B_), 128>>>();
    red1_kernel  <<<128, 128>>>();
    red2_kernel  <<<1, 128>>>(gamma, beta);
    final_kernel <<<dim3(S_ / 64, B_), 256>>>(out);
}